// round 10
// baseline (speedup 1.0000x reference)
#include <cuda_runtime.h>
#include <cuda_bf16.h>
#include <float.h>

#define BB 64
#define TT 512
#define FF 8
#define KK 128
#define NF 500000

// Scratch (device globals — no allocation allowed in kernel_launch)
__device__ float g_expT[KK * KK];                       // exp(transitions), row-major [i][j]
__device__ float g_em[(size_t)BB * TT * KK];            // emissions [b][t][k], 16.8 MB

// ---------------------------------------------------------------------------
// packed f32x2 helpers (sm_103a FFMA2 path)
// ---------------------------------------------------------------------------
__device__ __forceinline__ unsigned long long pack2(float lo, float hi) {
    unsigned long long u;
    asm("mov.b64 %0, {%1, %2};" : "=l"(u) : "f"(lo), "f"(hi));
    return u;
}
__device__ __forceinline__ float2 unpack2(unsigned long long u) {
    float2 v;
    asm("mov.b64 {%0, %1}, %2;" : "=f"(v.x), "=f"(v.y) : "l"(u));
    return v;
}
__device__ __forceinline__ void fma2(unsigned long long& d, unsigned long long a, unsigned long long b) {
    asm("fma.rn.f32x2 %0, %1, %2, %0;" : "+l"(d) : "l"(a), "l"(b));
}

// ---------------------------------------------------------------------------
// Kernel 1: expT = exp(transitions)   (tiny)
// ---------------------------------------------------------------------------
__global__ void expT_kernel(const float* __restrict__ trans) {
    int idx = blockIdx.x * blockDim.x + threadIdx.x;
    if (idx < KK * KK) g_expT[idx] = __expf(trans[idx]);
}

// ---------------------------------------------------------------------------
// Kernel 2: emissions gather. One CTA per (b,t); thread k sums 8 gathered
// weights from row k of state_weights.
// ---------------------------------------------------------------------------
__global__ void __launch_bounds__(KK) emis_kernel(const int* __restrict__ feats,
                                                  const float* __restrict__ sw) {
    int bt = blockIdx.x;
    __shared__ int sIdx[FF];
    if (threadIdx.x < FF) sIdx[threadIdx.x] = feats[bt * FF + threadIdx.x];
    __syncthreads();
    int k = threadIdx.x;
    const float* row = sw + (size_t)k * NF;
    float s = 0.f;
#pragma unroll
    for (int f = 0; f < FF; f++) s += __ldg(row + sIdx[f]);
    g_em[(size_t)bt * KK + k] = s;
}

// ---------------------------------------------------------------------------
// Kernel 3: forward recursion (linear-space GEMV per step) + gold score.
// 64 CTAs (one per sequence), 256 threads: thread (j, half) owns the partial
// dot over i in [half*64, half*64+64) with expT column j held in registers.
// ---------------------------------------------------------------------------
__global__ void __launch_bounds__(256, 1) crf_forward_kernel(
    const float* __restrict__ trans,
    const float* __restrict__ start_t,
    const float* __restrict__ end_t,
    const int* __restrict__ tags,
    float* __restrict__ out) {
    const int b = blockIdx.x;
    const int tid = threadIdx.x;
    const int j = tid & (KK - 1);
    const int half = tid >> 7;
    const int lane = tid & 31;
    const int wid = tid >> 5;
    const int rbase = half * 64;

    __shared__ __align__(16) float sE[KK];
    __shared__ float sRed[8];
    __shared__ float sG[8];
    __shared__ float sPart[256];
    __shared__ int sTags[TT];

    // stage tags for the gold score (overlaps nothing critical)
    for (int t = tid; t < TT; t += 256) sTags[t] = tags[b * TT + t];

    // load expT column j (rows rbase..rbase+63) into registers, packed x2
    unsigned long long c2[32];
#pragma unroll
    for (int i = 0; i < 32; i++) {
        float lo = g_expT[(rbase + 2 * i) * KK + j];
        float hi = g_expT[(rbase + 2 * i + 1) * KK + j];
        c2[i] = pack2(lo, hi);
    }

    const float* em = g_em + (size_t)b * TT * KK;

    float a = 0.f;
    float em_next = 0.f;
    if (tid < KK) {
        a = start_t[j] + em[j];         // alpha0
        em_next = em[KK + j];           // prefetch t=1 emissions
    }
    __syncthreads();                    // covers sTags staging

    for (int t = 1; t < TT; t++) {
        float em_cur = em_next;
        if (tid < KK && t + 1 < TT) em_next = em[(t + 1) * KK + j];  // prefetch

        // block max over alpha (lower half owns alpha)
        float w = (tid < KK) ? a : -FLT_MAX;
#pragma unroll
        for (int o = 16; o; o >>= 1) w = fmaxf(w, __shfl_xor_sync(0xffffffffu, w, o));
        if (lane == 0 && wid < 4) sRed[wid] = w;
        __syncthreads();
        float m = fmaxf(fmaxf(sRed[0], sRed[1]), fmaxf(sRed[2], sRed[3]));
        if (tid < KK) sE[j] = __expf(a - m);
        __syncthreads();

        // partial dot: Σ_i sE[i] * expT[i][j] over this thread's 64 rows
        unsigned long long acc0 = 0ull, acc1 = 0ull;
        const unsigned long long* sE2 =
            reinterpret_cast<const unsigned long long*>(sE + rbase);
#pragma unroll
        for (int i = 0; i < 32; i += 2) {
            fma2(acc0, sE2[i], c2[i]);
            fma2(acc1, sE2[i + 1], c2[i + 1]);
        }
        float2 a0 = unpack2(acc0), a1 = unpack2(acc1);
        sPart[tid] = (a0.x + a0.y) + (a1.x + a1.y);
        __syncthreads();

        if (tid < KK) {
            float s = sPart[j] + sPart[j + 128];
            a = em_cur + m + __logf(s);
        }
    }

    // logZ = logsumexp(alpha + end)
    float av = (tid < KK) ? (a + end_t[j]) : -FLT_MAX;
    float w = av;
#pragma unroll
    for (int o = 16; o; o >>= 1) w = fmaxf(w, __shfl_xor_sync(0xffffffffu, w, o));
    if (lane == 0 && wid < 4) sRed[wid] = w;
    __syncthreads();
    float m = fmaxf(fmaxf(sRed[0], sRed[1]), fmaxf(sRed[2], sRed[3]));
    float e = (tid < KK) ? __expf(av - m) : 0.f;
#pragma unroll
    for (int o = 16; o; o >>= 1) e += __shfl_xor_sync(0xffffffffu, e, o);
    if (lane == 0 && wid < 4) sRed[4 + wid] = e;
    __syncthreads();
    float logZ = m + __logf(sRed[4] + sRed[5] + sRed[6] + sRed[7]);

    // gold score
    float g = 0.f;
    for (int t = tid; t < TT; t += 256) {
        int tg = sTags[t];
        g += em[t * KK + tg];
        if (t + 1 < TT) g += trans[tg * KK + sTags[t + 1]];
    }
#pragma unroll
    for (int o = 16; o; o >>= 1) g += __shfl_xor_sync(0xffffffffu, g, o);
    if (lane == 0) sG[wid] = g;
    __syncthreads();
    if (tid == 0) {
        float gold = sG[0] + sG[1] + sG[2] + sG[3] + sG[4] + sG[5] + sG[6] + sG[7];
        gold += start_t[sTags[0]] + end_t[sTags[TT - 1]];
        out[b] = logZ - gold;
    }
}

// ---------------------------------------------------------------------------
extern "C" void kernel_launch(void* const* d_in, const int* in_sizes, int n_in,
                              void* d_out, int out_size) {
    const int*   feats = (const int*)d_in[0];
    const int*   tags  = (const int*)d_in[1];
    const float* sw    = (const float*)d_in[2];
    const float* trans = (const float*)d_in[3];
    const float* st    = (const float*)d_in[4];
    const float* en    = (const float*)d_in[5];
    float* out = (float*)d_out;

    expT_kernel<<<(KK * KK + 255) / 256, 256>>>(trans);
    emis_kernel<<<BB * TT, KK>>>(feats, sw);
    crf_forward_kernel<<<BB, 256>>>(trans, st, en, tags, out);
}

// round 11
// speedup vs baseline: 1.0006x; 1.0006x over previous
#include <cuda_runtime.h>
#include <cuda_bf16.h>
#include <float.h>

#define BB 64
#define TT 512
#define FF 8
#define KK 128
#define NF 500000

// Scratch (device globals — no allocation allowed in kernel_launch)
__device__ float g_expT[KK * KK];                       // exp(transitions), row-major [i][j]
__device__ float g_em[(size_t)BB * TT * KK];            // emissions [b][t][k], 16.8 MB

// ---------------------------------------------------------------------------
// packed f32x2 helpers (sm_103a FFMA2 path)
// ---------------------------------------------------------------------------
__device__ __forceinline__ unsigned long long pack2(float lo, float hi) {
    unsigned long long u;
    asm("mov.b64 %0, {%1, %2};" : "=l"(u) : "f"(lo), "f"(hi));
    return u;
}
__device__ __forceinline__ float2 unpack2(unsigned long long u) {
    float2 v;
    asm("mov.b64 {%0, %1}, %2;" : "=f"(v.x), "=f"(v.y) : "l"(u));
    return v;
}
__device__ __forceinline__ void fma2(unsigned long long& d, unsigned long long a, unsigned long long b) {
    asm("fma.rn.f32x2 %0, %1, %2, %0;" : "+l"(d) : "l"(a), "l"(b));
}

// ---------------------------------------------------------------------------
// Kernel 1: expT = exp(transitions)   (tiny)
// ---------------------------------------------------------------------------
__global__ void expT_kernel(const float* __restrict__ trans) {
    int idx = blockIdx.x * blockDim.x + threadIdx.x;
    if (idx < KK * KK) g_expT[idx] = __expf(trans[idx]);
}

// ---------------------------------------------------------------------------
// Kernel 2: emissions gather. One CTA per (b,t); thread k sums 8 gathered
// weights from row k of state_weights.
// ---------------------------------------------------------------------------
__global__ void __launch_bounds__(KK) emis_kernel(const int* __restrict__ feats,
                                                  const float* __restrict__ sw) {
    int bt = blockIdx.x;
    __shared__ int sIdx[FF];
    if (threadIdx.x < FF) sIdx[threadIdx.x] = feats[bt * FF + threadIdx.x];
    __syncthreads();
    int k = threadIdx.x;
    const float* row = sw + (size_t)k * NF;
    float s = 0.f;
#pragma unroll
    for (int f = 0; f < FF; f++) s += __ldg(row + sIdx[f]);
    g_em[(size_t)bt * KK + k] = s;
}

// ---------------------------------------------------------------------------
// Kernel 3: forward recursion (linear-space GEMV per step) + gold score.
// 64 CTAs (one per sequence), 256 threads: thread (j, half) owns the partial
// dot over i in [half*64, half*64+64) with expT column j held in registers.
// ---------------------------------------------------------------------------
__global__ void __launch_bounds__(256, 1) crf_forward_kernel(
    const float* __restrict__ trans,
    const float* __restrict__ start_t,
    const float* __restrict__ end_t,
    const int* __restrict__ tags,
    float* __restrict__ out) {
    const int b = blockIdx.x;
    const int tid = threadIdx.x;
    const int j = tid & (KK - 1);
    const int half = tid >> 7;
    const int lane = tid & 31;
    const int wid = tid >> 5;
    const int rbase = half * 64;

    __shared__ __align__(16) float sE[KK];
    __shared__ float sRed[8];
    __shared__ float sG[8];
    __shared__ float sPart[256];
    __shared__ int sTags[TT];

    // stage tags for the gold score (overlaps nothing critical)
    for (int t = tid; t < TT; t += 256) sTags[t] = tags[b * TT + t];

    // load expT column j (rows rbase..rbase+63) into registers, packed x2
    unsigned long long c2[32];
#pragma unroll
    for (int i = 0; i < 32; i++) {
        float lo = g_expT[(rbase + 2 * i) * KK + j];
        float hi = g_expT[(rbase + 2 * i + 1) * KK + j];
        c2[i] = pack2(lo, hi);
    }

    const float* em = g_em + (size_t)b * TT * KK;

    float a = 0.f;
    float em_next = 0.f;
    if (tid < KK) {
        a = start_t[j] + em[j];         // alpha0
        em_next = em[KK + j];           // prefetch t=1 emissions
    }
    __syncthreads();                    // covers sTags staging

    for (int t = 1; t < TT; t++) {
        float em_cur = em_next;
        if (tid < KK && t + 1 < TT) em_next = em[(t + 1) * KK + j];  // prefetch

        // block max over alpha (lower half owns alpha)
        float w = (tid < KK) ? a : -FLT_MAX;
#pragma unroll
        for (int o = 16; o; o >>= 1) w = fmaxf(w, __shfl_xor_sync(0xffffffffu, w, o));
        if (lane == 0 && wid < 4) sRed[wid] = w;
        __syncthreads();
        float m = fmaxf(fmaxf(sRed[0], sRed[1]), fmaxf(sRed[2], sRed[3]));
        if (tid < KK) sE[j] = __expf(a - m);
        __syncthreads();

        // partial dot: Σ_i sE[i] * expT[i][j] over this thread's 64 rows
        unsigned long long acc0 = 0ull, acc1 = 0ull;
        const unsigned long long* sE2 =
            reinterpret_cast<const unsigned long long*>(sE + rbase);
#pragma unroll
        for (int i = 0; i < 32; i += 2) {
            fma2(acc0, sE2[i], c2[i]);
            fma2(acc1, sE2[i + 1], c2[i + 1]);
        }
        float2 a0 = unpack2(acc0), a1 = unpack2(acc1);
        sPart[tid] = (a0.x + a0.y) + (a1.x + a1.y);
        __syncthreads();

        if (tid < KK) {
            float s = sPart[j] + sPart[j + 128];
            a = em_cur + m + __logf(s);
        }
    }

    // logZ = logsumexp(alpha + end)
    float av = (tid < KK) ? (a + end_t[j]) : -FLT_MAX;
    float w = av;
#pragma unroll
    for (int o = 16; o; o >>= 1) w = fmaxf(w, __shfl_xor_sync(0xffffffffu, w, o));
    if (lane == 0 && wid < 4) sRed[wid] = w;
    __syncthreads();
    float m = fmaxf(fmaxf(sRed[0], sRed[1]), fmaxf(sRed[2], sRed[3]));
    float e = (tid < KK) ? __expf(av - m) : 0.f;
#pragma unroll
    for (int o = 16; o; o >>= 1) e += __shfl_xor_sync(0xffffffffu, e, o);
    if (lane == 0 && wid < 4) sRed[4 + wid] = e;
    __syncthreads();
    float logZ = m + __logf(sRed[4] + sRed[5] + sRed[6] + sRed[7]);

    // gold score
    float g = 0.f;
    for (int t = tid; t < TT; t += 256) {
        int tg = sTags[t];
        g += em[t * KK + tg];
        if (t + 1 < TT) g += trans[tg * KK + sTags[t + 1]];
    }
#pragma unroll
    for (int o = 16; o; o >>= 1) g += __shfl_xor_sync(0xffffffffu, g, o);
    if (lane == 0) sG[wid] = g;
    __syncthreads();
    if (tid == 0) {
        float gold = sG[0] + sG[1] + sG[2] + sG[3] + sG[4] + sG[5] + sG[6] + sG[7];
        gold += start_t[sTags[0]] + end_t[sTags[TT - 1]];
        out[b] = logZ - gold;
    }
}

// ---------------------------------------------------------------------------
extern "C" void kernel_launch(void* const* d_in, const int* in_sizes, int n_in,
                              void* d_out, int out_size) {
    const int*   feats = (const int*)d_in[0];
    const int*   tags  = (const int*)d_in[1];
    const float* sw    = (const float*)d_in[2];
    const float* trans = (const float*)d_in[3];
    const float* st    = (const float*)d_in[4];
    const float* en    = (const float*)d_in[5];
    float* out = (float*)d_out;

    expT_kernel<<<(KK * KK + 255) / 256, 256>>>(trans);
    emis_kernel<<<BB * TT, KK>>>(feats, sw);
    crf_forward_kernel<<<BB, 256>>>(trans, st, en, tags, out);
}

// round 12
// speedup vs baseline: 1.0033x; 1.0027x over previous
#include <cuda_runtime.h>
#include <cuda_bf16.h>
#include <float.h>

#define BB 64
#define TT 512
#define FF 8
#define KK 128
#define NF 500000

// Scratch (device globals — no allocation allowed in kernel_launch)
__device__ float g_expT[KK * KK];                       // exp(transitions), row-major [i][j]
__device__ float g_em[(size_t)BB * TT * KK];            // emissions [b][t][k], 16.8 MB

// ---------------------------------------------------------------------------
// packed f32x2 helpers (sm_103a FFMA2 path)
// ---------------------------------------------------------------------------
__device__ __forceinline__ unsigned long long pack2(float lo, float hi) {
    unsigned long long u;
    asm("mov.b64 %0, {%1, %2};" : "=l"(u) : "f"(lo), "f"(hi));
    return u;
}
__device__ __forceinline__ float2 unpack2(unsigned long long u) {
    float2 v;
    asm("mov.b64 {%0, %1}, %2;" : "=f"(v.x), "=f"(v.y) : "l"(u));
    return v;
}
__device__ __forceinline__ void fma2(unsigned long long& d, unsigned long long a, unsigned long long b) {
    asm("fma.rn.f32x2 %0, %1, %2, %0;" : "+l"(d) : "l"(a), "l"(b));
}

// ---------------------------------------------------------------------------
// Kernel 1: expT = exp(transitions)   (tiny)
// ---------------------------------------------------------------------------
__global__ void expT_kernel(const float* __restrict__ trans) {
    int idx = blockIdx.x * blockDim.x + threadIdx.x;
    if (idx < KK * KK) g_expT[idx] = __expf(trans[idx]);
}

// ---------------------------------------------------------------------------
// Kernel 2: emissions gather. One CTA per (b,t); thread k sums 8 gathered
// weights from row k of state_weights.
// ---------------------------------------------------------------------------
__global__ void __launch_bounds__(KK) emis_kernel(const int* __restrict__ feats,
                                                  const float* __restrict__ sw) {
    int bt = blockIdx.x;
    __shared__ int sIdx[FF];
    if (threadIdx.x < FF) sIdx[threadIdx.x] = feats[bt * FF + threadIdx.x];
    __syncthreads();
    int k = threadIdx.x;
    const float* row = sw + (size_t)k * NF;
    float s = 0.f;
#pragma unroll
    for (int f = 0; f < FF; f++) s += __ldg(row + sIdx[f]);
    g_em[(size_t)bt * KK + k] = s;
}

// ---------------------------------------------------------------------------
// Kernel 3: forward recursion (linear-space GEMV per step) + gold score.
// 64 CTAs (one per sequence), 256 threads: thread (j, half) owns the partial
// dot over i in [half*64, half*64+64) with expT column j held in registers.
// ---------------------------------------------------------------------------
__global__ void __launch_bounds__(256, 1) crf_forward_kernel(
    const float* __restrict__ trans,
    const float* __restrict__ start_t,
    const float* __restrict__ end_t,
    const int* __restrict__ tags,
    float* __restrict__ out) {
    const int b = blockIdx.x;
    const int tid = threadIdx.x;
    const int j = tid & (KK - 1);
    const int half = tid >> 7;
    const int lane = tid & 31;
    const int wid = tid >> 5;
    const int rbase = half * 64;

    __shared__ __align__(16) float sE[KK];
    __shared__ float sRed[8];
    __shared__ float sG[8];
    __shared__ float sPart[256];
    __shared__ int sTags[TT];

    // stage tags for the gold score (overlaps nothing critical)
    for (int t = tid; t < TT; t += 256) sTags[t] = tags[b * TT + t];

    // load expT column j (rows rbase..rbase+63) into registers, packed x2
    unsigned long long c2[32];
#pragma unroll
    for (int i = 0; i < 32; i++) {
        float lo = g_expT[(rbase + 2 * i) * KK + j];
        float hi = g_expT[(rbase + 2 * i + 1) * KK + j];
        c2[i] = pack2(lo, hi);
    }

    const float* em = g_em + (size_t)b * TT * KK;

    float a = 0.f;
    float em_next = 0.f;
    if (tid < KK) {
        a = start_t[j] + em[j];         // alpha0
        em_next = em[KK + j];           // prefetch t=1 emissions
    }
    __syncthreads();                    // covers sTags staging

    for (int t = 1; t < TT; t++) {
        float em_cur = em_next;
        if (tid < KK && t + 1 < TT) em_next = em[(t + 1) * KK + j];  // prefetch

        // block max over alpha (lower half owns alpha)
        float w = (tid < KK) ? a : -FLT_MAX;
#pragma unroll
        for (int o = 16; o; o >>= 1) w = fmaxf(w, __shfl_xor_sync(0xffffffffu, w, o));
        if (lane == 0 && wid < 4) sRed[wid] = w;
        __syncthreads();
        float m = fmaxf(fmaxf(sRed[0], sRed[1]), fmaxf(sRed[2], sRed[3]));
        if (tid < KK) sE[j] = __expf(a - m);
        __syncthreads();

        // partial dot: Σ_i sE[i] * expT[i][j] over this thread's 64 rows
        unsigned long long acc0 = 0ull, acc1 = 0ull;
        const unsigned long long* sE2 =
            reinterpret_cast<const unsigned long long*>(sE + rbase);
#pragma unroll
        for (int i = 0; i < 32; i += 2) {
            fma2(acc0, sE2[i], c2[i]);
            fma2(acc1, sE2[i + 1], c2[i + 1]);
        }
        float2 a0 = unpack2(acc0), a1 = unpack2(acc1);
        sPart[tid] = (a0.x + a0.y) + (a1.x + a1.y);
        __syncthreads();

        if (tid < KK) {
            float s = sPart[j] + sPart[j + 128];
            a = em_cur + m + __logf(s);
        }
    }

    // logZ = logsumexp(alpha + end)
    float av = (tid < KK) ? (a + end_t[j]) : -FLT_MAX;
    float w = av;
#pragma unroll
    for (int o = 16; o; o >>= 1) w = fmaxf(w, __shfl_xor_sync(0xffffffffu, w, o));
    if (lane == 0 && wid < 4) sRed[wid] = w;
    __syncthreads();
    float m = fmaxf(fmaxf(sRed[0], sRed[1]), fmaxf(sRed[2], sRed[3]));
    float e = (tid < KK) ? __expf(av - m) : 0.f;
#pragma unroll
    for (int o = 16; o; o >>= 1) e += __shfl_xor_sync(0xffffffffu, e, o);
    if (lane == 0 && wid < 4) sRed[4 + wid] = e;
    __syncthreads();
    float logZ = m + __logf(sRed[4] + sRed[5] + sRed[6] + sRed[7]);

    // gold score
    float g = 0.f;
    for (int t = tid; t < TT; t += 256) {
        int tg = sTags[t];
        g += em[t * KK + tg];
        if (t + 1 < TT) g += trans[tg * KK + sTags[t + 1]];
    }
#pragma unroll
    for (int o = 16; o; o >>= 1) g += __shfl_xor_sync(0xffffffffu, g, o);
    if (lane == 0) sG[wid] = g;
    __syncthreads();
    if (tid == 0) {
        float gold = sG[0] + sG[1] + sG[2] + sG[3] + sG[4] + sG[5] + sG[6] + sG[7];
        gold += start_t[sTags[0]] + end_t[sTags[TT - 1]];
        out[b] = logZ - gold;
    }
}

// ---------------------------------------------------------------------------
extern "C" void kernel_launch(void* const* d_in, const int* in_sizes, int n_in,
                              void* d_out, int out_size) {
    const int*   feats = (const int*)d_in[0];
    const int*   tags  = (const int*)d_in[1];
    const float* sw    = (const float*)d_in[2];
    const float* trans = (const float*)d_in[3];
    const float* st    = (const float*)d_in[4];
    const float* en    = (const float*)d_in[5];
    float* out = (float*)d_out;

    expT_kernel<<<(KK * KK + 255) / 256, 256>>>(trans);
    emis_kernel<<<BB * TT, KK>>>(feats, sw);
    crf_forward_kernel<<<BB, 256>>>(trans, st, en, tags, out);
}